// round 1
// baseline (speedup 1.0000x reference)
#include <cuda_runtime.h>
#include <cuda_bf16.h>
#include <cstdint>

// TrellisLinear: out = x @ dequant(packed, grid, scales, su, sv)
//   x      [M,K]   f32
//   packed [K,N/2] i32 (each element is a byte: low nibble -> even n, high -> odd n)
//   grid   [16]    f32 codebook
//   scales [K/128, N] f32
//   su     [K]     f32
//   sv     [N]     f32
//   out    [M,N]   f32
//
// Fused GEMM: A-tile = x*su staged transposed in smem; B-tile dequantized into
// smem via a 256-entry byte->float2 codebook LUT, folding scales[g][n]*sv[n].

#define BM 128
#define BN 128
#define BK 32
#define TM 8
#define TN 8
#define APAD 4   // pad A row stride to keep 16B alignment of float4 reads

__global__ __launch_bounds__(256) void trellis_gemm_kernel(
    const float* __restrict__ x,
    const int*   __restrict__ packed,
    const float* __restrict__ grid,
    const float* __restrict__ scales,
    const float* __restrict__ su,
    const float* __restrict__ sv,
    float* __restrict__ out,
    int M, int K, int N)
{
    __shared__ float  As[BK][BM + APAD];  // [k][m] (transposed), stride 132 floats
    __shared__ float  Bs[BK][BN];         // [k][n]
    __shared__ float2 tab[256];           // byte -> (grid[lo], grid[hi])

    const int tid = threadIdx.x;
    const int mbase = blockIdx.x * BM;
    const int nbase = blockIdx.y * BN;
    const int npack = N >> 1;

    // Build the nibble-pair lookup table once per block.
    tab[tid & 255] = make_float2(grid[tid & 15], grid[(tid >> 4) & 15]);

    // B staging: 32 rows x 64 int32; 8 threads per row, 8 ints each.
    const int brow = tid >> 3;            // 0..31 (k within tile)
    const int bcol = (tid & 7) * 8;       // int32 index within row
    // Compute mapping: 16x16 thread grid, each thread an 8x8 micro-tile.
    const int ty = tid >> 4;
    const int tx = tid & 15;

    float acc[TM][TN];
    #pragma unroll
    for (int i = 0; i < TM; i++)
        #pragma unroll
        for (int j = 0; j < TN; j++)
            acc[i][j] = 0.f;

    for (int k0 = 0; k0 < K; k0 += BK) {
        __syncthreads();   // covers tab init on first iter, tile reuse after

        // ---- Stage A: As[k][m] = x[m][k] * su[k] (transposed store) ----
        #pragma unroll
        for (int i = 0; i < 4; i++) {
            int idx = tid + i * 256;          // 0..1023 float4 slots
            int row = idx >> 3;               // m row within tile (0..127)
            int c4  = (idx & 7) * 4;          // k within tile (0..28 step 4)
            const float4 xv = *reinterpret_cast<const float4*>(
                &x[(size_t)(mbase + row) * K + k0 + c4]);
            const float4 s4 = *reinterpret_cast<const float4*>(&su[k0 + c4]);
            As[c4 + 0][row] = xv.x * s4.x;
            As[c4 + 1][row] = xv.y * s4.y;
            As[c4 + 2][row] = xv.z * s4.z;
            As[c4 + 3][row] = xv.w * s4.w;
        }

        // ---- Stage B: dequant packed -> Bs[k][n], fold scales*sv ----
        {
            const int g = (k0 + brow) >> 7;   // scale group (GROUP=128)
            const int* prow = &packed[(size_t)(k0 + brow) * npack + (nbase >> 1) + bcol];
            const int4 p0 = *reinterpret_cast<const int4*>(prow);
            const int4 p1 = *reinterpret_cast<const int4*>(prow + 4);
            const int nloc = bcol * 2;        // local n base (16 outputs)
            const float* scp = &scales[(size_t)g * N + nbase + nloc];
            const float* svp = &sv[nbase + nloc];
            int pb[8] = {p0.x, p0.y, p0.z, p0.w, p1.x, p1.y, p1.z, p1.w};
            #pragma unroll
            for (int j = 0; j < 8; j++) {
                const float2 w = tab[pb[j] & 255];
                const float s0 = scp[2 * j]     * svp[2 * j];
                const float s1 = scp[2 * j + 1] * svp[2 * j + 1];
                Bs[brow][nloc + 2 * j]     = w.x * s0;
                Bs[brow][nloc + 2 * j + 1] = w.y * s1;
            }
        }
        __syncthreads();

        // ---- Compute: 8x8 register tile over 32 k-steps ----
        #pragma unroll 8
        for (int kk = 0; kk < BK; kk++) {
            float a[TM], b[TN];
            *reinterpret_cast<float4*>(&a[0]) =
                *reinterpret_cast<const float4*>(&As[kk][ty * TM]);
            *reinterpret_cast<float4*>(&a[4]) =
                *reinterpret_cast<const float4*>(&As[kk][ty * TM + 4]);
            *reinterpret_cast<float4*>(&b[0]) =
                *reinterpret_cast<const float4*>(&Bs[kk][tx * TN]);
            *reinterpret_cast<float4*>(&b[4]) =
                *reinterpret_cast<const float4*>(&Bs[kk][tx * TN + 4]);
            #pragma unroll
            for (int i = 0; i < TM; i++)
                #pragma unroll
                for (int j = 0; j < TN; j++)
                    acc[i][j] = fmaf(a[i], b[j], acc[i][j]);
        }
    }

    // ---- Epilogue: vectorized stores ----
    #pragma unroll
    for (int i = 0; i < TM; i++) {
        float4* o = reinterpret_cast<float4*>(
            &out[(size_t)(mbase + ty * TM + i) * N + nbase + tx * TN]);
        o[0] = make_float4(acc[i][0], acc[i][1], acc[i][2], acc[i][3]);
        o[1] = make_float4(acc[i][4], acc[i][5], acc[i][6], acc[i][7]);
    }
}

extern "C" void kernel_launch(void* const* d_in, const int* in_sizes, int n_in,
                              void* d_out, int out_size)
{
    const float* x      = (const float*)d_in[0];
    const int*   packed = (const int*)  d_in[1];
    const float* grid   = (const float*)d_in[2];
    const float* scales = (const float*)d_in[3];
    const float* su     = (const float*)d_in[4];
    const float* sv     = (const float*)d_in[5];
    float* out = (float*)d_out;

    const int K = in_sizes[4];          // su length
    const int N = in_sizes[5];          // sv length
    const int M = in_sizes[0] / K;      // x is [M,K]

    dim3 grd(M / BM, N / BN);
    trellis_gemm_kernel<<<grd, 256>>>(x, packed, grid, scales, su, sv, out,
                                      M, K, N);
}

// round 3
// speedup vs baseline: 2.2102x; 2.2102x over previous
#include <cuda_runtime.h>
#include <cuda_bf16.h>
#include <cstdint>

// ============ problem constants ============
#define M_FIXED 512
#define K_FIXED 8192
#define N_FIXED 8192
#define NPACK   (N_FIXED / 2)

#define BM 128
#define BN 128
#define BK 64
#define NTHREADS 256   // 8 warps: 2 (m) x 4 (n), warp tile 64x32

// Precomputed A = x*su split into bf16 hi/lo, row-major [M][K]
__device__ __nv_bfloat16 g_Ah[M_FIXED * (size_t)K_FIXED];
__device__ __nv_bfloat16 g_Al[M_FIXED * (size_t)K_FIXED];

// ============ smem layout (bytes) ============
#define SM_TAB 0                    // float2[256] = 2048
#define SM_AH  2048                 // 128 rows x 128 B (SW128)
#define SM_AL  (SM_AH + 16384)
#define SM_BH  (SM_AL + 16384)      // B^T: 128 n-rows x 128 B (64 bf16 k)
#define SM_BL  (SM_BH + 16384)
#define SMEM_TOTAL (SM_BL + 16384)  // 67584

#define SW128(off) ((off) ^ (((off) >> 3) & 0x70))

__device__ __forceinline__ uint32_t smem_u32(const void* p) {
    uint32_t a;
    asm("{ .reg .u64 t; cvta.to.shared.u64 t, %1; cvt.u32.u64 %0, t; }" : "=r"(a) : "l"(p));
    return a;
}
__device__ __forceinline__ void cp_async16(uint32_t dst, const void* src) {
    asm volatile("cp.async.cg.shared.global [%0], [%1], 16;" :: "r"(dst), "l"(src));
}
__device__ __forceinline__ void ldsm4(uint32_t& r0, uint32_t& r1, uint32_t& r2,
                                      uint32_t& r3, uint32_t addr) {
    asm volatile("ldmatrix.sync.aligned.m8n8.x4.shared.b16 {%0,%1,%2,%3}, [%4];"
                 : "=r"(r0), "=r"(r1), "=r"(r2), "=r"(r3) : "r"(addr));
}
__device__ __forceinline__ void mma16816(float* d, const uint32_t* a, const uint32_t* b) {
    asm volatile(
        "mma.sync.aligned.m16n8k16.row.col.f32.bf16.bf16.f32 "
        "{%0,%1,%2,%3}, {%4,%5,%6,%7}, {%8,%9}, {%0,%1,%2,%3};"
        : "+f"(d[0]), "+f"(d[1]), "+f"(d[2]), "+f"(d[3])
        : "r"(a[0]), "r"(a[1]), "r"(a[2]), "r"(a[3]), "r"(b[0]), "r"(b[1]));
}

// ============ kernel 1: A = x * su -> bf16 hi/lo ============
__global__ __launch_bounds__(256) void precompute_a(const float* __restrict__ x,
                                                    const float* __restrict__ su) {
    int i4 = blockIdx.x * 256 + threadIdx.x;
    size_t base = (size_t)i4 * 4;
    int k = (int)(base & (K_FIXED - 1));
    float4 xv = *reinterpret_cast<const float4*>(x + base);
    float4 s  = *reinterpret_cast<const float4*>(su + k);
    float a[4] = {xv.x * s.x, xv.y * s.y, xv.z * s.z, xv.w * s.w};
    uint32_t hp[2], lp[2];
    #pragma unroll
    for (int j = 0; j < 2; j++) {
        __nv_bfloat16 h0 = __float2bfloat16_rn(a[2 * j]);
        __nv_bfloat16 h1 = __float2bfloat16_rn(a[2 * j + 1]);
        __nv_bfloat16 l0 = __float2bfloat16_rn(a[2 * j]     - __bfloat162float(h0));
        __nv_bfloat16 l1 = __float2bfloat16_rn(a[2 * j + 1] - __bfloat162float(h1));
        hp[j] = (uint32_t)__bfloat16_as_ushort(h0) | ((uint32_t)__bfloat16_as_ushort(h1) << 16);
        lp[j] = (uint32_t)__bfloat16_as_ushort(l0) | ((uint32_t)__bfloat16_as_ushort(l1) << 16);
    }
    *reinterpret_cast<uint2*>(reinterpret_cast<char*>(g_Ah) + base * 2) = make_uint2(hp[0], hp[1]);
    *reinterpret_cast<uint2*>(reinterpret_cast<char*>(g_Al) + base * 2) = make_uint2(lp[0], lp[1]);
}

// ============ kernel 2: HMMA GEMM with fused dequant ============
__global__ __launch_bounds__(NTHREADS) void trellis_mma_kernel(
    const int*   __restrict__ packed,
    const float* __restrict__ grid,
    const float* __restrict__ scales,
    const float* __restrict__ sv,
    float*       __restrict__ out)
{
    extern __shared__ char smem[];
    const uint32_t sbase = smem_u32(smem);
    float2* tab = reinterpret_cast<float2*>(smem + SM_TAB);

    const int tid = threadIdx.x;
    const int lid = tid & 31;
    const int wid = tid >> 5;
    const int mw  = wid >> 2;       // 0..1 -> m offset 64*mw
    const int nw  = wid & 3;        // 0..3 -> n offset 32*nw
    const int mbase = blockIdx.x * BM;
    const int nbase = blockIdx.y * BN;

    if (tid < 256) tab[tid] = make_float2(grid[tid & 15], grid[(tid >> 4) & 15]);

    // B dequant identity: n-pair np (0..63), k-groups kg and kg+4
    const int np = tid & 63;
    const int kgb = tid >> 6;       // 0..3
    const int n0 = 2 * np;

    // ldmatrix lane addressing (unswizzled base offsets within a tile)
    const int arow = (lid & 15);
    const int khalf = (lid >> 4) * 16;   // byte offset of k-half

    float acc[4][4][4];
    #pragma unroll
    for (int mi = 0; mi < 4; mi++)
        #pragma unroll
        for (int ni = 0; ni < 4; ni++)
            #pragma unroll
            for (int v = 0; v < 4; v++) acc[mi][ni][v] = 0.f;

    for (int k0 = 0; k0 < K_FIXED; k0 += BK) {
        __syncthreads();   // tiles free (covers tab init on iter 0)

        // ---- stage A hi/lo via cp.async: 2048 x 16B chunks / 256 thr = 8 each
        #pragma unroll
        for (int i = 0; i < 8; i++) {
            int q = tid + i * NTHREADS;
            int copy = q >> 10;            // 0 hi, 1 lo
            int r = q & 1023;
            int row = r >> 3;
            int c16 = r & 7;
            const __nv_bfloat16* src = (copy ? g_Al : g_Ah) +
                (size_t)(mbase + row) * K_FIXED + k0 + c16 * 8;
            uint32_t dst = sbase + (copy ? SM_AL : SM_AH) +
                           SW128((uint32_t)(row * 128 + c16 * 16));
            cp_async16(dst, src);
        }
        asm volatile("cp.async.commit_group;" ::: "memory");

        // ---- dequant B (overlapped with cp.async) ----
        {
            const int g = k0 >> 7;
            const float sc0 = scales[(size_t)g * N_FIXED + nbase + n0]     * sv[nbase + n0];
            const float sc1 = scales[(size_t)g * N_FIXED + nbase + n0 + 1] * sv[nbase + n0 + 1];
            #pragma unroll
            for (int s = 0; s < 2; s++) {
                const int kg = kgb + s * 4;          // 0..7
                const int* prow = packed + (size_t)(k0 + kg * 8) * NPACK + (nbase >> 1) + np;
                int pb[8];
                #pragma unroll
                for (int j = 0; j < 8; j++) pb[j] = prow[(size_t)j * NPACK];

                uint32_t h0[4], h1[4], l0[4], l1[4];
                #pragma unroll
                for (int j = 0; j < 4; j++) {
                    float2 wa = tab[pb[2 * j] & 255];       // k = 2j
                    float2 wb = tab[pb[2 * j + 1] & 255];   // k = 2j+1
                    float a0 = wa.x * sc0, b0 = wb.x * sc0; // n0, k even/odd
                    float a1 = wa.y * sc1, b1 = wb.y * sc1; // n1
                    __nv_bfloat16 ha0 = __float2bfloat16_rn(a0);
                    __nv_bfloat16 hb0 = __float2bfloat16_rn(b0);
                    __nv_bfloat16 ha1 = __float2bfloat16_rn(a1);
                    __nv_bfloat16 hb1 = __float2bfloat16_rn(b1);
                    __nv_bfloat16 la0 = __float2bfloat16_rn(a0 - __bfloat162float(ha0));
                    __nv_bfloat16 lb0 = __float2bfloat16_rn(b0 - __bfloat162float(hb0));
                    __nv_bfloat16 la1 = __float2bfloat16_rn(a1 - __bfloat162float(ha1));
                    __nv_bfloat16 lb1 = __float2bfloat16_rn(b1 - __bfloat162float(hb1));
                    h0[j] = (uint32_t)__bfloat16_as_ushort(ha0) |
                            ((uint32_t)__bfloat16_as_ushort(hb0) << 16);
                    h1[j] = (uint32_t)__bfloat16_as_ushort(ha1) |
                            ((uint32_t)__bfloat16_as_ushort(hb1) << 16);
                    l0[j] = (uint32_t)__bfloat16_as_ushort(la0) |
                            ((uint32_t)__bfloat16_as_ushort(lb0) << 16);
                    l1[j] = (uint32_t)__bfloat16_as_ushort(la1) |
                            ((uint32_t)__bfloat16_as_ushort(lb1) << 16);
                }
                uint32_t o0 = SW128((uint32_t)(n0 * 128 + kg * 16));
                uint32_t o1 = SW128((uint32_t)((n0 + 1) * 128 + kg * 16));
                *reinterpret_cast<uint4*>(smem + SM_BH + o0) = make_uint4(h0[0], h0[1], h0[2], h0[3]);
                *reinterpret_cast<uint4*>(smem + SM_BH + o1) = make_uint4(h1[0], h1[1], h1[2], h1[3]);
                *reinterpret_cast<uint4*>(smem + SM_BL + o0) = make_uint4(l0[0], l0[1], l0[2], l0[3]);
                *reinterpret_cast<uint4*>(smem + SM_BL + o1) = make_uint4(l1[0], l1[1], l1[2], l1[3]);
            }
        }

        asm volatile("cp.async.wait_group 0;" ::: "memory");
        __syncthreads();

        // ---- MMA: 4 k16 steps x (AhBh + AhBl + AlBh) ----
        #pragma unroll
        for (int kk = 0; kk < 4; kk++) {
            const uint32_t kb = kk * 32 + khalf;
            uint32_t ah[4][4], al[4][4], bhf[4][2], blf[4][2];
            #pragma unroll
            for (int mi = 0; mi < 4; mi++) {
                uint32_t off = SW128((uint32_t)((mw * 64 + mi * 16 + arow) * 128) + kb);
                ldsm4(ah[mi][0], ah[mi][1], ah[mi][2], ah[mi][3], sbase + SM_AH + off);
                ldsm4(al[mi][0], al[mi][1], al[mi][2], al[mi][3], sbase + SM_AL + off);
            }
            #pragma unroll
            for (int nj = 0; nj < 2; nj++) {
                uint32_t off = SW128((uint32_t)((nw * 32 + nj * 16 + arow) * 128) + kb);
                uint32_t r0, r1, r2, r3;
                ldsm4(r0, r1, r2, r3, sbase + SM_BH + off);
                bhf[2 * nj][0] = r0; bhf[2 * nj][1] = r2;
                bhf[2 * nj + 1][0] = r1; bhf[2 * nj + 1][1] = r3;
                ldsm4(r0, r1, r2, r3, sbase + SM_BL + off);
                blf[2 * nj][0] = r0; blf[2 * nj][1] = r2;
                blf[2 * nj + 1][0] = r1; blf[2 * nj + 1][1] = r3;
            }
            #pragma unroll
            for (int mi = 0; mi < 4; mi++)
                #pragma unroll
                for (int ni = 0; ni < 4; ni++)
                    mma16816(acc[mi][ni], ah[mi], bhf[ni]);
            #pragma unroll
            for (int mi = 0; mi < 4; mi++)
                #pragma unroll
                for (int ni = 0; ni < 4; ni++)
                    mma16816(acc[mi][ni], ah[mi], blf[ni]);
            #pragma unroll
            for (int mi = 0; mi < 4; mi++)
                #pragma unroll
                for (int ni = 0; ni < 4; ni++)
                    mma16816(acc[mi][ni], al[mi], bhf[ni]);
        }
    }

    // ---- epilogue ----
    const int er = lid >> 2;
    const int ec = (lid & 3) * 2;
    #pragma unroll
    for (int mi = 0; mi < 4; mi++) {
        #pragma unroll
        for (int ni = 0; ni < 4; ni++) {
            int row = mbase + mw * 64 + mi * 16 + er;
            int col = nbase + nw * 32 + ni * 8 + ec;
            *reinterpret_cast<float2*>(out + (size_t)row * N_FIXED + col) =
                make_float2(acc[mi][ni][0], acc[mi][ni][1]);
            *reinterpret_cast<float2*>(out + (size_t)(row + 8) * N_FIXED + col) =
                make_float2(acc[mi][ni][2], acc[mi][ni][3]);
        }
    }
}

// ============ host launcher ============
extern "C" void kernel_launch(void* const* d_in, const int* in_sizes, int n_in,
                              void* d_out, int out_size)
{
    const float* x      = (const float*)d_in[0];
    const int*   packed = (const int*)  d_in[1];
    const float* grid   = (const float*)d_in[2];
    const float* scales = (const float*)d_in[3];
    const float* su     = (const float*)d_in[4];
    const float* sv     = (const float*)d_in[5];
    float* out = (float*)d_out;

    cudaFuncSetAttribute(trellis_mma_kernel,
                         cudaFuncAttributeMaxDynamicSharedMemorySize, SMEM_TOTAL);

    precompute_a<<<(M_FIXED * K_FIXED) / 1024, 256>>>(x, su);

    dim3 grd(M_FIXED / BM, N_FIXED / BN);
    trellis_mma_kernel<<<grd, NTHREADS, SMEM_TOTAL>>>(packed, grid, scales, sv, out);
}

// round 4
// speedup vs baseline: 2.6684x; 1.2073x over previous
#include <cuda_runtime.h>
#include <cuda_bf16.h>
#include <cstdint>

// ============ problem constants ============
#define M_FIXED 512
#define K_FIXED 8192
#define N_FIXED 8192
#define NPACK   (N_FIXED / 2)

#define BM 128
#define BN 128
#define BK 64
#define NTHREADS 256   // 8 warps: 2 (m) x 4 (n), warp tile 64x32

// Precomputed A = x*su split into bf16 hi/lo, row-major [M][K]
__device__ __nv_bfloat16 g_Ah[M_FIXED * (size_t)K_FIXED];
__device__ __nv_bfloat16 g_Al[M_FIXED * (size_t)K_FIXED];

// ============ smem layout (bytes) ============
#define SM_TAB 0                    // float2[256] = 2048
#define SM_AH  2048                 // 128 rows x 128 B (SW128)
#define SM_AL  (SM_AH + 16384)
#define SM_BH  (SM_AL + 16384)      // B^T: 128 n-rows x 128 B (64 bf16 k)
#define SM_BL  (SM_BH + 16384)
#define SMEM_TOTAL (SM_BL + 16384)  // 67584 -> 2 CTAs/SM fit (135KB < 228KB)

#define SW128(off) ((off) ^ (((off) >> 3) & 0x70))

__device__ __forceinline__ uint32_t smem_u32(const void* p) {
    uint32_t a;
    asm("{ .reg .u64 t; cvta.to.shared.u64 t, %1; cvt.u32.u64 %0, t; }" : "=r"(a) : "l"(p));
    return a;
}
__device__ __forceinline__ void cp_async16(uint32_t dst, const void* src) {
    asm volatile("cp.async.cg.shared.global [%0], [%1], 16;" :: "r"(dst), "l"(src));
}
__device__ __forceinline__ void ldsm4(uint32_t& r0, uint32_t& r1, uint32_t& r2,
                                      uint32_t& r3, uint32_t addr) {
    asm volatile("ldmatrix.sync.aligned.m8n8.x4.shared.b16 {%0,%1,%2,%3}, [%4];"
                 : "=r"(r0), "=r"(r1), "=r"(r2), "=r"(r3) : "r"(addr));
}
__device__ __forceinline__ void mma16816(float* d, const uint32_t* a, const uint32_t* b) {
    asm volatile(
        "mma.sync.aligned.m16n8k16.row.col.f32.bf16.bf16.f32 "
        "{%0,%1,%2,%3}, {%4,%5,%6,%7}, {%8,%9}, {%0,%1,%2,%3};"
        : "+f"(d[0]), "+f"(d[1]), "+f"(d[2]), "+f"(d[3])
        : "r"(a[0]), "r"(a[1]), "r"(a[2]), "r"(a[3]), "r"(b[0]), "r"(b[1]));
}
__device__ __forceinline__ uint32_t bf2pack(float lo, float hi) {
    __nv_bfloat162 v = __floats2bfloat162_rn(lo, hi);
    return *reinterpret_cast<uint32_t*>(&v);
}

// ============ kernel 1: A = x * su -> bf16 hi/lo ============
__global__ __launch_bounds__(256) void precompute_a(const float* __restrict__ x,
                                                    const float* __restrict__ su) {
    int i4 = blockIdx.x * 256 + threadIdx.x;
    size_t base = (size_t)i4 * 4;
    int k = (int)(base & (K_FIXED - 1));
    float4 xv = *reinterpret_cast<const float4*>(x + base);
    float4 s  = *reinterpret_cast<const float4*>(su + k);
    float a[4] = {xv.x * s.x, xv.y * s.y, xv.z * s.z, xv.w * s.w};
    uint32_t hp[2], lp[2];
    #pragma unroll
    for (int j = 0; j < 2; j++) {
        float f0 = a[2 * j], f1 = a[2 * j + 1];
        hp[j] = bf2pack(f0, f1);
        __nv_bfloat162 h = *reinterpret_cast<__nv_bfloat162*>(&hp[j]);
        lp[j] = bf2pack(f0 - __bfloat162float(h.x), f1 - __bfloat162float(h.y));
    }
    *reinterpret_cast<uint2*>(reinterpret_cast<char*>(g_Ah) + base * 2) = make_uint2(hp[0], hp[1]);
    *reinterpret_cast<uint2*>(reinterpret_cast<char*>(g_Al) + base * 2) = make_uint2(lp[0], lp[1]);
}

// ============ kernel 2: HMMA GEMM with fused dequant (2 CTAs/SM) ============
__global__ __launch_bounds__(NTHREADS, 2) void trellis_mma_kernel(
    const int*   __restrict__ packed,
    const float* __restrict__ grid,
    const float* __restrict__ scales,
    const float* __restrict__ sv,
    float*       __restrict__ out)
{
    extern __shared__ char smem[];
    const uint32_t sbase = smem_u32(smem);
    float2* tab = reinterpret_cast<float2*>(smem + SM_TAB);

    const int tid = threadIdx.x;
    const int lid = tid & 31;
    const int wid = tid >> 5;
    const int mw  = wid >> 2;       // 0..1 -> m offset 64*mw
    const int nw  = wid & 3;        // 0..3 -> n offset 32*nw
    const int mbase = blockIdx.x * BM;
    const int nbase = blockIdx.y * BN;

    if (tid < 256) tab[tid] = make_float2(grid[tid & 15], grid[(tid >> 4) & 15]);

    // B dequant identity: n-pair np (0..63), k-groups kgb and kgb+4
    const int np = tid & 63;
    const int kgb = tid >> 6;       // 0..3
    const int n0 = 2 * np;

    // ldmatrix lane addressing
    const int arow = (lid & 15);
    const int khalf = (lid >> 4) * 16;   // byte offset of k-half

    float acc[4][4][4];
    #pragma unroll
    for (int mi = 0; mi < 4; mi++)
        #pragma unroll
        for (int ni = 0; ni < 4; ni++)
            #pragma unroll
            for (int v = 0; v < 4; v++) acc[mi][ni][v] = 0.f;

    for (int k0 = 0; k0 < K_FIXED; k0 += BK) {
        __syncthreads();   // tiles free (covers tab init on iter 0)

        // ---- issue packed LDGs for s=0 early (L2 latency overlap) ----
        const int g = k0 >> 7;
        const float sc0 = scales[(size_t)g * N_FIXED + nbase + n0]     * sv[nbase + n0];
        const float sc1 = scales[(size_t)g * N_FIXED + nbase + n0 + 1] * sv[nbase + n0 + 1];
        int pb[8];
        {
            const int* prow = packed + (size_t)(k0 + kgb * 8) * NPACK + (nbase >> 1) + np;
            #pragma unroll
            for (int j = 0; j < 8; j++) pb[j] = prow[(size_t)j * NPACK];
        }

        // ---- stage A hi/lo via cp.async: 2048 x 16B chunks / 256 thr = 8 each
        #pragma unroll
        for (int i = 0; i < 8; i++) {
            int q = tid + i * NTHREADS;
            int copy = q >> 10;            // 0 hi, 1 lo
            int r = q & 1023;
            int row = r >> 3;
            int c16 = r & 7;
            const __nv_bfloat16* src = (copy ? g_Al : g_Ah) +
                (size_t)(mbase + row) * K_FIXED + k0 + c16 * 8;
            uint32_t dst = sbase + (copy ? SM_AL : SM_AH) +
                           SW128((uint32_t)(row * 128 + c16 * 16));
            cp_async16(dst, src);
        }
        asm volatile("cp.async.commit_group;" ::: "memory");

        // ---- dequant B (two k-groups per thread) ----
        #pragma unroll
        for (int s = 0; s < 2; s++) {
            const int kg = kgb + s * 4;          // 0..7
            uint32_t h0[4], h1[4], l0[4], l1[4];
            #pragma unroll
            for (int j = 0; j < 4; j++) {
                float2 wa = tab[pb[2 * j] & 255];       // k = 2j
                float2 wb = tab[pb[2 * j + 1] & 255];   // k = 2j+1
                float a0 = wa.x * sc0, b0 = wb.x * sc0; // n0
                float a1 = wa.y * sc1, b1 = wb.y * sc1; // n1
                h0[j] = bf2pack(a0, b0);
                h1[j] = bf2pack(a1, b1);
                __nv_bfloat162 H0 = *reinterpret_cast<__nv_bfloat162*>(&h0[j]);
                __nv_bfloat162 H1 = *reinterpret_cast<__nv_bfloat162*>(&h1[j]);
                l0[j] = bf2pack(a0 - __bfloat162float(H0.x), b0 - __bfloat162float(H0.y));
                l1[j] = bf2pack(a1 - __bfloat162float(H1.x), b1 - __bfloat162float(H1.y));
            }
            // prefetch next k-group's packed while these STS retire
            if (s == 0) {
                const int* prow = packed + (size_t)(k0 + (kgb + 4) * 8) * NPACK + (nbase >> 1) + np;
                #pragma unroll
                for (int j = 0; j < 8; j++) pb[j] = prow[(size_t)j * NPACK];
            }
            uint32_t o0 = SW128((uint32_t)(n0 * 128 + kg * 16));
            uint32_t o1 = SW128((uint32_t)((n0 + 1) * 128 + kg * 16));
            *reinterpret_cast<uint4*>(smem + SM_BH + o0) = make_uint4(h0[0], h0[1], h0[2], h0[3]);
            *reinterpret_cast<uint4*>(smem + SM_BH + o1) = make_uint4(h1[0], h1[1], h1[2], h1[3]);
            *reinterpret_cast<uint4*>(smem + SM_BL + o0) = make_uint4(l0[0], l0[1], l0[2], l0[3]);
            *reinterpret_cast<uint4*>(smem + SM_BL + o1) = make_uint4(l1[0], l1[1], l1[2], l1[3]);
        }

        asm volatile("cp.async.wait_group 0;" ::: "memory");
        __syncthreads();

        // ---- MMA: 4 k16 steps x (AhBh + AhBl + AlBh) ----
        #pragma unroll
        for (int kk = 0; kk < 4; kk++) {
            const uint32_t kb = kk * 32 + khalf;
            uint32_t bhf[4][2], blf[4][2];
            #pragma unroll
            for (int nj = 0; nj < 2; nj++) {
                uint32_t off = SW128((uint32_t)((nw * 32 + nj * 16 + arow) * 128) + kb);
                uint32_t r0, r1, r2, r3;
                ldsm4(r0, r1, r2, r3, sbase + SM_BH + off);
                bhf[2 * nj][0] = r0; bhf[2 * nj][1] = r2;
                bhf[2 * nj + 1][0] = r1; bhf[2 * nj + 1][1] = r3;
                ldsm4(r0, r1, r2, r3, sbase + SM_BL + off);
                blf[2 * nj][0] = r0; blf[2 * nj][1] = r2;
                blf[2 * nj + 1][0] = r1; blf[2 * nj + 1][1] = r3;
            }
            #pragma unroll
            for (int mi = 0; mi < 4; mi++) {
                uint32_t ah[4], al[4];
                uint32_t off = SW128((uint32_t)((mw * 64 + mi * 16 + arow) * 128) + kb);
                ldsm4(ah[0], ah[1], ah[2], ah[3], sbase + SM_AH + off);
                ldsm4(al[0], al[1], al[2], al[3], sbase + SM_AL + off);
                #pragma unroll
                for (int ni = 0; ni < 4; ni++)
                    mma16816(acc[mi][ni], ah, bhf[ni]);
                #pragma unroll
                for (int ni = 0; ni < 4; ni++)
                    mma16816(acc[mi][ni], ah, blf[ni]);
                #pragma unroll
                for (int ni = 0; ni < 4; ni++)
                    mma16816(acc[mi][ni], al, bhf[ni]);
            }
        }
    }

    // ---- epilogue ----
    const int er = lid >> 2;
    const int ec = (lid & 3) * 2;
    #pragma unroll
    for (int mi = 0; mi < 4; mi++) {
        #pragma unroll
        for (int ni = 0; ni < 4; ni++) {
            int row = mbase + mw * 64 + mi * 16 + er;
            int col = nbase + nw * 32 + ni * 8 + ec;
            *reinterpret_cast<float2*>(out + (size_t)row * N_FIXED + col) =
                make_float2(acc[mi][ni][0], acc[mi][ni][1]);
            *reinterpret_cast<float2*>(out + (size_t)(row + 8) * N_FIXED + col) =
                make_float2(acc[mi][ni][2], acc[mi][ni][3]);
        }
    }
}

// ============ host launcher ============
extern "C" void kernel_launch(void* const* d_in, const int* in_sizes, int n_in,
                              void* d_out, int out_size)
{
    const float* x      = (const float*)d_in[0];
    const int*   packed = (const int*)  d_in[1];
    const float* grid   = (const float*)d_in[2];
    const float* scales = (const float*)d_in[3];
    const float* su     = (const float*)d_in[4];
    const float* sv     = (const float*)d_in[5];
    float* out = (float*)d_out;

    cudaFuncSetAttribute(trellis_mma_kernel,
                         cudaFuncAttributeMaxDynamicSharedMemorySize, SMEM_TOTAL);

    precompute_a<<<(M_FIXED * K_FIXED) / 1024, 256>>>(x, su);

    dim3 grd(M_FIXED / BM, N_FIXED / BN);
    trellis_mma_kernel<<<grd, NTHREADS, SMEM_TOTAL>>>(packed, grid, scales, sv, out);
}

// round 5
// speedup vs baseline: 3.0058x; 1.1265x over previous
#include <cuda_runtime.h>
#include <cuda_bf16.h>
#include <cstdint>

// ============ problem constants ============
#define M_FIXED 512
#define K_FIXED 8192
#define N_FIXED 8192
#define NPACK   (N_FIXED / 2)

#define BM 128
#define BN 128
#define BK 32
#define NTHREADS 256   // 8 warps: 2 (m) x 4 (n), warp tile 64x32
#define NK (K_FIXED / BK)

// Precomputed A = x*su split into bf16 hi/lo, row-major [M][K]
__device__ __nv_bfloat16 g_Ah[M_FIXED * (size_t)K_FIXED];
__device__ __nv_bfloat16 g_Al[M_FIXED * (size_t)K_FIXED];

// ============ smem layout (bytes) ============
// Tile row format: 128 B = [32 bf16 hi | 32 bf16 lo], SW128-swizzled.
#define SM_TAB 0                     // float2[256] = 2048
#define SM_A   2048                  // 2 stages x 128 rows x 128 B
#define SM_B   (SM_A + 2 * 16384)    // 2 stages x 128 rows x 128 B
#define SMEM_TOTAL (SM_B + 2 * 16384)   // 67584 -> 2 CTAs/SM

#define SW128(off) ((off) ^ (((off) >> 3) & 0x70))

__device__ __forceinline__ uint32_t smem_u32(const void* p) {
    uint32_t a;
    asm("{ .reg .u64 t; cvta.to.shared.u64 t, %1; cvt.u32.u64 %0, t; }" : "=r"(a) : "l"(p));
    return a;
}
__device__ __forceinline__ void cp_async16(uint32_t dst, const void* src) {
    asm volatile("cp.async.cg.shared.global [%0], [%1], 16;" :: "r"(dst), "l"(src));
}
__device__ __forceinline__ void ldsm4(uint32_t& r0, uint32_t& r1, uint32_t& r2,
                                      uint32_t& r3, uint32_t addr) {
    asm volatile("ldmatrix.sync.aligned.m8n8.x4.shared.b16 {%0,%1,%2,%3}, [%4];"
                 : "=r"(r0), "=r"(r1), "=r"(r2), "=r"(r3) : "r"(addr));
}
__device__ __forceinline__ void mma16816(float* d, const uint32_t* a, const uint32_t* b) {
    asm volatile(
        "mma.sync.aligned.m16n8k16.row.col.f32.bf16.bf16.f32 "
        "{%0,%1,%2,%3}, {%4,%5,%6,%7}, {%8,%9}, {%0,%1,%2,%3};"
        : "+f"(d[0]), "+f"(d[1]), "+f"(d[2]), "+f"(d[3])
        : "r"(a[0]), "r"(a[1]), "r"(a[2]), "r"(a[3]), "r"(b[0]), "r"(b[1]));
}
__device__ __forceinline__ uint32_t bf2pack(float lo, float hi) {
    __nv_bfloat162 v = __floats2bfloat162_rn(lo, hi);
    return *reinterpret_cast<uint32_t*>(&v);
}

// ============ kernel 1: A = x * su -> bf16 hi/lo ============
__global__ __launch_bounds__(256) void precompute_a(const float* __restrict__ x,
                                                    const float* __restrict__ su) {
    int i4 = blockIdx.x * 256 + threadIdx.x;
    size_t base = (size_t)i4 * 4;
    int k = (int)(base & (K_FIXED - 1));
    float4 xv = *reinterpret_cast<const float4*>(x + base);
    float4 s  = *reinterpret_cast<const float4*>(su + k);
    float a[4] = {xv.x * s.x, xv.y * s.y, xv.z * s.z, xv.w * s.w};
    uint32_t hp[2], lp[2];
    #pragma unroll
    for (int j = 0; j < 2; j++) {
        float f0 = a[2 * j], f1 = a[2 * j + 1];
        hp[j] = bf2pack(f0, f1);
        __nv_bfloat162 h = *reinterpret_cast<__nv_bfloat162*>(&hp[j]);
        lp[j] = bf2pack(f0 - __bfloat162float(h.x), f1 - __bfloat162float(h.y));
    }
    *reinterpret_cast<uint2*>(reinterpret_cast<char*>(g_Ah) + base * 2) = make_uint2(hp[0], hp[1]);
    *reinterpret_cast<uint2*>(reinterpret_cast<char*>(g_Al) + base * 2) = make_uint2(lp[0], lp[1]);
}

// ============ dequant helper: 8 packed ints -> 4 STS.128 into B tile ====
__device__ __forceinline__ void dequant_sts(const int* pb, const float2* tab,
                                            float sc0, float sc1,
                                            char* bbase, int n0, int kg)
{
    uint32_t h0[4], h1[4], l0[4], l1[4];
    #pragma unroll
    for (int j = 0; j < 4; j++) {
        float2 wa = tab[pb[2 * j] & 255];       // k = 2j
        float2 wb = tab[pb[2 * j + 1] & 255];   // k = 2j+1
        float a0 = wa.x * sc0, b0 = wb.x * sc0; // n0
        float a1 = wa.y * sc1, b1 = wb.y * sc1; // n1
        h0[j] = bf2pack(a0, b0);
        h1[j] = bf2pack(a1, b1);
        __nv_bfloat162 H0 = *reinterpret_cast<__nv_bfloat162*>(&h0[j]);
        __nv_bfloat162 H1 = *reinterpret_cast<__nv_bfloat162*>(&h1[j]);
        l0[j] = bf2pack(a0 - __bfloat162float(H0.x), b0 - __bfloat162float(H0.y));
        l1[j] = bf2pack(a1 - __bfloat162float(H1.x), b1 - __bfloat162float(H1.y));
    }
    uint32_t oh0 = SW128((uint32_t)(n0 * 128 + kg * 16));
    uint32_t oh1 = SW128((uint32_t)((n0 + 1) * 128 + kg * 16));
    uint32_t ol0 = SW128((uint32_t)(n0 * 128 + 64 + kg * 16));
    uint32_t ol1 = SW128((uint32_t)((n0 + 1) * 128 + 64 + kg * 16));
    *reinterpret_cast<uint4*>(bbase + oh0) = make_uint4(h0[0], h0[1], h0[2], h0[3]);
    *reinterpret_cast<uint4*>(bbase + oh1) = make_uint4(h1[0], h1[1], h1[2], h1[3]);
    *reinterpret_cast<uint4*>(bbase + ol0) = make_uint4(l0[0], l0[1], l0[2], l0[3]);
    *reinterpret_cast<uint4*>(bbase + ol1) = make_uint4(l1[0], l1[1], l1[2], l1[3]);
}

// ============ kernel 2: pipelined HMMA GEMM with fused dequant ============
__global__ __launch_bounds__(NTHREADS, 2) void trellis_mma_kernel(
    const int*   __restrict__ packed,
    const float* __restrict__ grid,
    const float* __restrict__ scales,
    const float* __restrict__ sv,
    float*       __restrict__ out)
{
    extern __shared__ char smem[];
    const uint32_t sbase = smem_u32(smem);
    float2* tab = reinterpret_cast<float2*>(smem + SM_TAB);

    const int tid = threadIdx.x;
    const int lid = tid & 31;
    const int wid = tid >> 5;
    const int mw  = wid >> 2;       // 0..1 -> m offset 64*mw
    const int nw  = wid & 3;        // 0..3 -> n offset 32*nw
    const int mbase = blockIdx.x * BM;
    const int nbase = blockIdx.y * BN;

    tab[tid] = make_float2(grid[tid & 15], grid[(tid >> 4) & 15]);

    // B dequant identity
    const int np = tid & 63;        // n-pair 0..63
    const int kg = tid >> 6;        // k-group 0..3 (k = kg*8..+7)
    const int n0 = 2 * np;
    const int* pcol = packed + (size_t)kg * 8 * NPACK + (nbase >> 1) + np;
    const float* scp0 = scales + nbase + n0;
    const float sv0 = sv[nbase + n0], sv1 = sv[nbase + n0 + 1];

    // ldmatrix lane addressing
    const int arow = (lid & 15);
    const int khalf = (lid >> 4) * 16;

    float acc[4][4][4];
    #pragma unroll
    for (int mi = 0; mi < 4; mi++)
        #pragma unroll
        for (int ni = 0; ni < 4; ni++)
            #pragma unroll
            for (int v = 0; v < 4; v++) acc[mi][ni][v] = 0.f;

    // A staging: 4 x 16B chunks per thread per iter
    auto stage_A = [&](int k0, int stage) {
        #pragma unroll
        for (int i = 0; i < 4; i++) {
            int q = tid + i * NTHREADS;     // 0..1023
            int row = q >> 3;
            int half = (q >> 2) & 1;        // 0 hi, 1 lo
            int c = q & 3;                  // 16B chunk within half
            const __nv_bfloat16* src = (half ? g_Al : g_Ah) +
                (size_t)(mbase + row) * K_FIXED + k0 + c * 8;
            uint32_t dst = sbase + SM_A + stage * 16384 +
                           SW128((uint32_t)(row * 128 + half * 64 + c * 16));
            cp_async16(dst, src);
        }
        asm volatile("cp.async.commit_group;" ::: "memory");
    };

    // ---- prologue: stage iter 0 into stage 0 ----
    {
        float sc0 = scp0[0] * sv0, sc1 = scp0[1] * sv1;
        int pb[8];
        #pragma unroll
        for (int j = 0; j < 8; j++) pb[j] = pcol[(size_t)j * NPACK];
        stage_A(0, 0);
        __syncthreads();   // tab ready before LUT use
        dequant_sts(pb, tab, sc0, sc1, smem + SM_B, n0, kg);
        asm volatile("cp.async.wait_group 0;" ::: "memory");
        __syncthreads();
    }

    for (int i = 0; i < NK; i++) {
        const int p = i & 1;
        const int q = p ^ 1;
        const uint32_t abase = sbase + SM_A + p * 16384;
        const uint32_t bbase = sbase + SM_B + p * 16384;

        // ---- prefetch iter i+1 (LDG + cp.async issue before MMA) ----
        int pb[8];
        float sc0 = 0.f, sc1 = 0.f;
        const bool more = (i + 1 < NK);
        if (more) {
            const int k1 = (i + 1) * BK;
            const int g = k1 >> 7;
            sc0 = scp0[(size_t)g * N_FIXED]     * sv0;
            sc1 = scp0[(size_t)g * N_FIXED + 1] * sv1;
            const int* prow = pcol + (size_t)k1 * NPACK;
            #pragma unroll
            for (int j = 0; j < 8; j++) pb[j] = prow[(size_t)j * NPACK];
            stage_A(k1, q);
        }

        // ---- MMA for iter i: 2 k16 steps x (AhBh + AhBl + AlBh) ----
        #pragma unroll
        for (int kk = 0; kk < 2; kk++) {
            const uint32_t kbh = kk * 32 + khalf;
            uint32_t bhf[4][2], blf[4][2];
            #pragma unroll
            for (int nj = 0; nj < 2; nj++) {
                uint32_t ro = (uint32_t)((nw * 32 + nj * 16 + arow) * 128);
                uint32_t r0, r1, r2, r3;
                ldsm4(r0, r1, r2, r3, bbase + SW128(ro + kbh));
                bhf[2 * nj][0] = r0; bhf[2 * nj][1] = r2;
                bhf[2 * nj + 1][0] = r1; bhf[2 * nj + 1][1] = r3;
                ldsm4(r0, r1, r2, r3, bbase + SW128(ro + kbh + 64));
                blf[2 * nj][0] = r0; blf[2 * nj][1] = r2;
                blf[2 * nj + 1][0] = r1; blf[2 * nj + 1][1] = r3;
            }
            #pragma unroll
            for (int mi = 0; mi < 4; mi++) {
                uint32_t ah[4], al[4];
                uint32_t ro = (uint32_t)((mw * 64 + mi * 16 + arow) * 128);
                ldsm4(ah[0], ah[1], ah[2], ah[3], abase + SW128(ro + kbh));
                ldsm4(al[0], al[1], al[2], al[3], abase + SW128(ro + kbh + 64));
                #pragma unroll
                for (int ni = 0; ni < 4; ni++)
                    mma16816(acc[mi][ni], ah, bhf[ni]);
                #pragma unroll
                for (int ni = 0; ni < 4; ni++)
                    mma16816(acc[mi][ni], ah, blf[ni]);
                #pragma unroll
                for (int ni = 0; ni < 4; ni++)
                    mma16816(acc[mi][ni], al, bhf[ni]);
            }
        }

        // ---- dequant iter i+1 into stage q ----
        if (more) {
            dequant_sts(pb, tab, sc0, sc1, smem + SM_B + q * 16384, n0, kg);
            asm volatile("cp.async.wait_group 0;" ::: "memory");
        }
        __syncthreads();
    }

    // ---- epilogue ----
    const int er = lid >> 2;
    const int ec = (lid & 3) * 2;
    #pragma unroll
    for (int mi = 0; mi < 4; mi++) {
        #pragma unroll
        for (int ni = 0; ni < 4; ni++) {
            int row = mbase + mw * 64 + mi * 16 + er;
            int col = nbase + nw * 32 + ni * 8 + ec;
            *reinterpret_cast<float2*>(out + (size_t)row * N_FIXED + col) =
                make_float2(acc[mi][ni][0], acc[mi][ni][1]);
            *reinterpret_cast<float2*>(out + (size_t)(row + 8) * N_FIXED + col) =
                make_float2(acc[mi][ni][2], acc[mi][ni][3]);
        }
    }
}

// ============ host launcher ============
extern "C" void kernel_launch(void* const* d_in, const int* in_sizes, int n_in,
                              void* d_out, int out_size)
{
    const float* x      = (const float*)d_in[0];
    const int*   packed = (const int*)  d_in[1];
    const float* grid   = (const float*)d_in[2];
    const float* scales = (const float*)d_in[3];
    const float* su     = (const float*)d_in[4];
    const float* sv     = (const float*)d_in[5];
    float* out = (float*)d_out;

    cudaFuncSetAttribute(trellis_mma_kernel,
                         cudaFuncAttributeMaxDynamicSharedMemorySize, SMEM_TOTAL);

    precompute_a<<<(M_FIXED * K_FIXED) / 1024, 256>>>(x, su);

    dim3 grd(M_FIXED / BM, N_FIXED / BN);
    trellis_mma_kernel<<<grd, NTHREADS, SMEM_TOTAL>>>(packed, grid, scales, sv, out);
}

// round 6
// speedup vs baseline: 6.1998x; 2.0626x over previous
#include <cuda_runtime.h>
#include <cuda_fp16.h>
#include <cstdint>

// ============ problem constants ============
#define M_FIXED 512
#define K_FIXED 8192
#define N_FIXED 8192
#define NPACK   (N_FIXED / 2)

#define BM 128
#define BN 128
#define BK 64
#define NTHREADS 256   // 8 warps: 2 (m) x 4 (n), warp tile 64x32
#define NK (K_FIXED / BK)

// Precomputed A = x*su in fp16, row-major [M][K]
__device__ __half g_A[M_FIXED * (size_t)K_FIXED];

// ============ smem layout (bytes) ============
// Tile row = 128 B = 64 fp16 along k, SW128-swizzled.
#define SM_TAB 0                     // float2[256] = 2048
#define SM_A   2048                  // 2 stages x 128 rows x 128 B
#define SM_B   (SM_A + 2 * 16384)
#define SMEM_TOTAL (SM_B + 2 * 16384)   // 67584 -> 2 CTAs/SM

#define SW128(off) ((off) ^ (((off) >> 3) & 0x70))

__device__ __forceinline__ uint32_t smem_u32(const void* p) {
    uint32_t a;
    asm("{ .reg .u64 t; cvta.to.shared.u64 t, %1; cvt.u32.u64 %0, t; }" : "=r"(a) : "l"(p));
    return a;
}
__device__ __forceinline__ void cp_async16(uint32_t dst, const void* src) {
    asm volatile("cp.async.cg.shared.global [%0], [%1], 16;" :: "r"(dst), "l"(src));
}
__device__ __forceinline__ void ldsm4(uint32_t& r0, uint32_t& r1, uint32_t& r2,
                                      uint32_t& r3, uint32_t addr) {
    asm volatile("ldmatrix.sync.aligned.m8n8.x4.shared.b16 {%0,%1,%2,%3}, [%4];"
                 : "=r"(r0), "=r"(r1), "=r"(r2), "=r"(r3) : "r"(addr));
}
__device__ __forceinline__ void mma16816(float* d, const uint32_t* a, const uint32_t* b) {
    asm volatile(
        "mma.sync.aligned.m16n8k16.row.col.f32.f16.f16.f32 "
        "{%0,%1,%2,%3}, {%4,%5,%6,%7}, {%8,%9}, {%0,%1,%2,%3};"
        : "+f"(d[0]), "+f"(d[1]), "+f"(d[2]), "+f"(d[3])
        : "r"(a[0]), "r"(a[1]), "r"(a[2]), "r"(a[3]), "r"(b[0]), "r"(b[1]));
}
__device__ __forceinline__ uint32_t h2pack(float lo, float hi) {
    __half2 v = __floats2half2_rn(lo, hi);
    return *reinterpret_cast<uint32_t*>(&v);
}

// ============ kernel 1: A = x * su -> fp16 ============
__global__ __launch_bounds__(256) void precompute_a(const float* __restrict__ x,
                                                    const float* __restrict__ su) {
    int i4 = blockIdx.x * 256 + threadIdx.x;
    size_t base = (size_t)i4 * 4;
    int k = (int)(base & (K_FIXED - 1));
    float4 xv = *reinterpret_cast<const float4*>(x + base);
    float4 s  = *reinterpret_cast<const float4*>(su + k);
    uint2 o;
    o.x = h2pack(xv.x * s.x, xv.y * s.y);
    o.y = h2pack(xv.z * s.z, xv.w * s.w);
    *reinterpret_cast<uint2*>(reinterpret_cast<char*>(g_A) + base * 2) = o;
}

// ============ dequant: 16 packed ints -> 4 STS.128 into B tile ====
__device__ __forceinline__ void dequant_sts(const int* pb, const float2* tab,
                                            float sc0, float sc1,
                                            char* bbase, int n0, int kg)
{
    uint32_t o0[8], o1[8];
    #pragma unroll
    for (int j = 0; j < 8; j++) {
        float2 wa = tab[pb[2 * j] & 255];       // k = 2j
        float2 wb = tab[pb[2 * j + 1] & 255];   // k = 2j+1
        o0[j] = h2pack(wa.x * sc0, wb.x * sc0); // row n0
        o1[j] = h2pack(wa.y * sc1, wb.y * sc1); // row n0+1
    }
    uint32_t b0 = (uint32_t)(n0 * 128 + kg * 32);
    uint32_t b1 = (uint32_t)((n0 + 1) * 128 + kg * 32);
    *reinterpret_cast<uint4*>(bbase + SW128(b0))      = make_uint4(o0[0], o0[1], o0[2], o0[3]);
    *reinterpret_cast<uint4*>(bbase + SW128(b0 + 16)) = make_uint4(o0[4], o0[5], o0[6], o0[7]);
    *reinterpret_cast<uint4*>(bbase + SW128(b1))      = make_uint4(o1[0], o1[1], o1[2], o1[3]);
    *reinterpret_cast<uint4*>(bbase + SW128(b1 + 16)) = make_uint4(o1[4], o1[5], o1[6], o1[7]);
}

// ============ kernel 2: pipelined fp16 HMMA GEMM with fused dequant ========
__global__ __launch_bounds__(NTHREADS, 2) void trellis_mma_kernel(
    const int*   __restrict__ packed,
    const float* __restrict__ grid,
    const float* __restrict__ scales,
    const float* __restrict__ sv,
    float*       __restrict__ out)
{
    extern __shared__ char smem[];
    const uint32_t sbase = smem_u32(smem);
    float2* tab = reinterpret_cast<float2*>(smem + SM_TAB);

    const int tid = threadIdx.x;
    const int lid = tid & 31;
    const int wid = tid >> 5;
    const int mw  = wid >> 2;       // 0..1 -> m offset 64*mw
    const int nw  = wid & 3;        // 0..3 -> n offset 32*nw
    const int mbase = blockIdx.x * BM;
    const int nbase = blockIdx.y * BN;

    tab[tid] = make_float2(grid[tid & 15], grid[(tid >> 4) & 15]);

    // B dequant identity: n-pair np, k-group of 16 (kg)
    const int np = tid & 63;
    const int kg = tid >> 6;        // 0..3, k = kg*16 .. +15
    const int n0 = 2 * np;
    const int* pcol = packed + (size_t)(kg * 16) * NPACK + (nbase >> 1) + np;
    const float* scp0 = scales + nbase + n0;
    const float sv0 = sv[nbase + n0], sv1 = sv[nbase + n0 + 1];

    // ldmatrix lane addressing
    const int arow = (lid & 15);
    const int khalf = (lid >> 4) * 16;

    float acc[4][4][4];
    #pragma unroll
    for (int mi = 0; mi < 4; mi++)
        #pragma unroll
        for (int ni = 0; ni < 4; ni++)
            #pragma unroll
            for (int v = 0; v < 4; v++) acc[mi][ni][v] = 0.f;

    // A staging: 1024 x 16B chunks / 256 thr = 4 each
    auto stage_A = [&](int k0, int stage) {
        #pragma unroll
        for (int i = 0; i < 4; i++) {
            int q = tid + i * NTHREADS;     // 0..1023
            int row = q >> 3;
            int c = q & 7;
            const __half* src = g_A + (size_t)(mbase + row) * K_FIXED + k0 + c * 8;
            uint32_t dst = sbase + SM_A + stage * 16384 +
                           SW128((uint32_t)(row * 128 + c * 16));
            cp_async16(dst, src);
        }
        asm volatile("cp.async.commit_group;" ::: "memory");
    };

    // ---- prologue: stage iter 0 into stage 0 ----
    {
        float sc0 = scp0[0] * sv0, sc1 = scp0[1] * sv1;
        int pb[16];
        #pragma unroll
        for (int j = 0; j < 16; j++) pb[j] = pcol[(size_t)j * NPACK];
        stage_A(0, 0);
        __syncthreads();   // tab ready before LUT use
        dequant_sts(pb, tab, sc0, sc1, smem + SM_B, n0, kg);
        asm volatile("cp.async.wait_group 0;" ::: "memory");
        __syncthreads();
    }

    for (int i = 0; i < NK; i++) {
        const int p = i & 1;
        const int q = p ^ 1;
        const uint32_t abase = sbase + SM_A + p * 16384;
        const uint32_t bbase = sbase + SM_B + p * 16384;

        // ---- prefetch iter i+1 (LDG + cp.async issue before MMA) ----
        int pb[16];
        float sc0 = 0.f, sc1 = 0.f;
        const bool more = (i + 1 < NK);
        if (more) {
            const int k1 = (i + 1) * BK;
            const int g = k1 >> 7;
            sc0 = scp0[(size_t)g * N_FIXED]     * sv0;
            sc1 = scp0[(size_t)g * N_FIXED + 1] * sv1;
            const int* prow = pcol + (size_t)k1 * NPACK;
            #pragma unroll
            for (int j = 0; j < 16; j++) pb[j] = prow[(size_t)j * NPACK];
            stage_A(k1, q);
        }

        // ---- MMA for iter i: 4 k16 steps, single fp16 term ----
        #pragma unroll
        for (int kk = 0; kk < 4; kk++) {
            const uint32_t kb = (uint32_t)(kk * 32 + khalf);
            uint32_t bf[4][2];
            #pragma unroll
            for (int nj = 0; nj < 2; nj++) {
                uint32_t ro = (uint32_t)((nw * 32 + nj * 16 + arow) * 128);
                uint32_t r0, r1, r2, r3;
                ldsm4(r0, r1, r2, r3, bbase + SW128(ro + kb));
                bf[2 * nj][0] = r0; bf[2 * nj][1] = r2;
                bf[2 * nj + 1][0] = r1; bf[2 * nj + 1][1] = r3;
            }
            #pragma unroll
            for (int mi = 0; mi < 4; mi++) {
                uint32_t ah[4];
                uint32_t ro = (uint32_t)((mw * 64 + mi * 16 + arow) * 128);
                ldsm4(ah[0], ah[1], ah[2], ah[3], abase + SW128(ro + kb));
                #pragma unroll
                for (int ni = 0; ni < 4; ni++)
                    mma16816(acc[mi][ni], ah, bf[ni]);
            }
        }

        // ---- dequant iter i+1 into stage q ----
        if (more) {
            dequant_sts(pb, tab, sc0, sc1, smem + SM_B + q * 16384, n0, kg);
            asm volatile("cp.async.wait_group 0;" ::: "memory");
        }
        __syncthreads();
    }

    // ---- epilogue ----
    const int er = lid >> 2;
    const int ec = (lid & 3) * 2;
    #pragma unroll
    for (int mi = 0; mi < 4; mi++) {
        #pragma unroll
        for (int ni = 0; ni < 4; ni++) {
            int row = mbase + mw * 64 + mi * 16 + er;
            int col = nbase + nw * 32 + ni * 8 + ec;
            *reinterpret_cast<float2*>(out + (size_t)row * N_FIXED + col) =
                make_float2(acc[mi][ni][0], acc[mi][ni][1]);
            *reinterpret_cast<float2*>(out + (size_t)(row + 8) * N_FIXED + col) =
                make_float2(acc[mi][ni][2], acc[mi][ni][3]);
        }
    }
}

// ============ host launcher ============
extern "C" void kernel_launch(void* const* d_in, const int* in_sizes, int n_in,
                              void* d_out, int out_size)
{
    const float* x      = (const float*)d_in[0];
    const int*   packed = (const int*)  d_in[1];
    const float* grid   = (const float*)d_in[2];
    const float* scales = (const float*)d_in[3];
    const float* su     = (const float*)d_in[4];
    const float* sv     = (const float*)d_in[5];
    float* out = (float*)d_out;

    cudaFuncSetAttribute(trellis_mma_kernel,
                         cudaFuncAttributeMaxDynamicSharedMemorySize, SMEM_TOTAL);

    precompute_a<<<(M_FIXED * K_FIXED) / 1024, 256>>>(x, su);

    dim3 grd(M_FIXED / BM, N_FIXED / BN);
    trellis_mma_kernel<<<grd, NTHREADS, SMEM_TOTAL>>>(packed, grid, scales, sv, out);
}

// round 7
// speedup vs baseline: 7.6318x; 1.2310x over previous
#include <cuda_runtime.h>
#include <cuda_fp16.h>
#include <cstdint>

// ============ problem constants ============
#define M_FIXED 512
#define K_FIXED 8192
#define N_FIXED 8192
#define NPACK   (N_FIXED / 2)

#define BM 256
#define BN 128
#define BK 64
#define NTHREADS 256   // 8 warps: 4 (m) x 2 (n), warp tile 64x64
#define NK (K_FIXED / BK)

// Precomputed A = x*su in fp16, row-major [M][K]
__device__ __half g_A[M_FIXED * (size_t)K_FIXED];

// ============ smem layout (bytes) ============
// Tile row = 128 B = 64 fp16 along k, SW128-swizzled.
#define SM_TAB 0                     // half2 tab, 4 copies x 256 x 4B = 4096
#define SM_A   4096                  // 2 stages x 256 rows x 128 B = 65536
#define SM_B   (SM_A + 2 * 32768)    // 2 stages x 128 rows x 128 B = 32768
#define SMEM_TOTAL (SM_B + 2 * 16384)   // 102400 B (1 CTA/SM)

#define SW128(off) ((off) ^ (((off) >> 3) & 0x70))

__device__ __forceinline__ uint32_t smem_u32(const void* p) {
    uint32_t a;
    asm("{ .reg .u64 t; cvta.to.shared.u64 t, %1; cvt.u32.u64 %0, t; }" : "=r"(a) : "l"(p));
    return a;
}
__device__ __forceinline__ void cp_async16(uint32_t dst, const void* src) {
    asm volatile("cp.async.cg.shared.global [%0], [%1], 16;" :: "r"(dst), "l"(src));
}
__device__ __forceinline__ void ldsm4(uint32_t& r0, uint32_t& r1, uint32_t& r2,
                                      uint32_t& r3, uint32_t addr) {
    asm volatile("ldmatrix.sync.aligned.m8n8.x4.shared.b16 {%0,%1,%2,%3}, [%4];"
                 : "=r"(r0), "=r"(r1), "=r"(r2), "=r"(r3) : "r"(addr));
}
__device__ __forceinline__ void mma16816(float* d, const uint32_t* a, const uint32_t* b) {
    asm volatile(
        "mma.sync.aligned.m16n8k16.row.col.f32.f16.f16.f32 "
        "{%0,%1,%2,%3}, {%4,%5,%6,%7}, {%8,%9}, {%0,%1,%2,%3};"
        : "+f"(d[0]), "+f"(d[1]), "+f"(d[2]), "+f"(d[3])
        : "r"(a[0]), "r"(a[1]), "r"(a[2]), "r"(a[3]), "r"(b[0]), "r"(b[1]));
}
__device__ __forceinline__ uint32_t h2pack(float lo, float hi) {
    __half2 v = __floats2half2_rn(lo, hi);
    return *reinterpret_cast<uint32_t*>(&v);
}
__device__ __forceinline__ uint32_t hmul2(uint32_t a, uint32_t b) {
    uint32_t r;
    asm("mul.f16x2 %0, %1, %2;" : "=r"(r) : "r"(a), "r"(b));
    return r;
}

// ============ kernel 1: A = x * su -> fp16 ============
__global__ __launch_bounds__(256) void precompute_a(const float* __restrict__ x,
                                                    const float* __restrict__ su) {
    int i4 = blockIdx.x * 256 + threadIdx.x;
    size_t base = (size_t)i4 * 4;
    int k = (int)(base & (K_FIXED - 1));
    float4 xv = *reinterpret_cast<const float4*>(x + base);
    float4 s  = *reinterpret_cast<const float4*>(su + k);
    uint2 o;
    o.x = h2pack(xv.x * s.x, xv.y * s.y);
    o.y = h2pack(xv.z * s.z, xv.w * s.w);
    *reinterpret_cast<uint2*>(reinterpret_cast<char*>(g_A) + base * 2) = o;
}

// ============ dequant: 16 packed ints -> 4 STS.128 into B tile ====
// tab entries: half2(grid[lo], grid[hi]) = weights for (n0, n0+1) at one k.
__device__ __forceinline__ void dequant_sts(const int* pb, const uint32_t* tabc,
                                            uint32_t hsc0, uint32_t hsc1,
                                            char* bbase, int n0, int kg)
{
    uint32_t o0[8], o1[8];
    #pragma unroll
    for (int j = 0; j < 8; j++) {
        uint32_t wa = tabc[pb[2 * j] & 255];       // k = 2j:   (n0, n1)
        uint32_t wb = tabc[pb[2 * j + 1] & 255];   // k = 2j+1: (n0, n1)
        uint32_t u0 = __byte_perm(wa, wb, 0x5410); // (wa.x, wb.x) = row n0, k pair
        uint32_t u1 = __byte_perm(wa, wb, 0x7632); // (wa.y, wb.y) = row n1, k pair
        o0[j] = hmul2(u0, hsc0);
        o1[j] = hmul2(u1, hsc1);
    }
    uint32_t b0 = (uint32_t)(n0 * 128 + kg * 32);
    uint32_t b1 = (uint32_t)((n0 + 1) * 128 + kg * 32);
    *reinterpret_cast<uint4*>(bbase + SW128(b0))      = make_uint4(o0[0], o0[1], o0[2], o0[3]);
    *reinterpret_cast<uint4*>(bbase + SW128(b0 + 16)) = make_uint4(o0[4], o0[5], o0[6], o0[7]);
    *reinterpret_cast<uint4*>(bbase + SW128(b1))      = make_uint4(o1[0], o1[1], o1[2], o1[3]);
    *reinterpret_cast<uint4*>(bbase + SW128(b1 + 16)) = make_uint4(o1[4], o1[5], o1[6], o1[7]);
}

// ============ kernel 2: pipelined fp16 HMMA GEMM, warp tile 64x64 ==========
__global__ __launch_bounds__(NTHREADS, 1) void trellis_mma_kernel(
    const int*   __restrict__ packed,
    const float* __restrict__ grid,
    const float* __restrict__ scales,
    const float* __restrict__ sv,
    float*       __restrict__ out)
{
    extern __shared__ char smem[];
    const uint32_t sbase = smem_u32(smem);
    uint32_t* tab = reinterpret_cast<uint32_t*>(smem + SM_TAB);

    const int tid = threadIdx.x;
    const int lid = tid & 31;
    const int wid = tid >> 5;
    const int mw  = wid >> 1;       // 0..3 -> m offset 64*mw
    const int nw  = wid & 1;        // 0..1 -> n offset 64*nw
    const int mbase = blockIdx.x * BM;
    const int nbase = blockIdx.y * BN;

    // Build 4 replicated half2 LUT copies: tab[c*256 + b] = h2(grid[lo], grid[hi])
    #pragma unroll
    for (int c = 0; c < 4; c++) {
        int b = tid & 255;  // 256 threads each write entry tid in all 4 copies
        tab[c * 256 + b] = h2pack(grid[b & 15], grid[(b >> 4) & 15]);
    }
    const uint32_t* tabc = tab + ((lid >> 3) & 3) * 256;  // lane-octet copy

    // B dequant identity: n-pair np (0..63), k-group of 16 (kg 0..3)
    const int np = tid & 63;
    const int kg = tid >> 6;
    const int n0 = 2 * np;
    const int* pcol = packed + (size_t)(kg * 16) * NPACK + (nbase >> 1) + np;
    const float* scp0 = scales + nbase + n0;
    const float sv0 = sv[nbase + n0], sv1 = sv[nbase + n0 + 1];

    // ldmatrix lane addressing
    const int arow = (lid & 15);
    const int khalf = (lid >> 4) * 16;

    float acc[4][8][4];
    #pragma unroll
    for (int mi = 0; mi < 4; mi++)
        #pragma unroll
        for (int ni = 0; ni < 8; ni++)
            #pragma unroll
            for (int v = 0; v < 4; v++) acc[mi][ni][v] = 0.f;

    // A staging: 2048 x 16B chunks / 256 thr = 8 each
    auto stage_A = [&](int k0, int stage) {
        #pragma unroll
        for (int i = 0; i < 8; i++) {
            int q = tid + i * NTHREADS;     // 0..2047
            int row = q >> 3;               // 0..255
            int c = q & 7;
            const __half* src = g_A + (size_t)(mbase + row) * K_FIXED + k0 + c * 8;
            uint32_t dst = sbase + SM_A + stage * 32768 +
                           SW128((uint32_t)(row * 128 + c * 16));
            cp_async16(dst, src);
        }
        asm volatile("cp.async.commit_group;" ::: "memory");
    };

    // ---- prologue: stage iter 0 into stage 0 ----
    {
        uint32_t hsc0, hsc1;
        {
            __half2 h0 = __float2half2_rn(scp0[0] * sv0);
            __half2 h1 = __float2half2_rn(scp0[1] * sv1);
            hsc0 = *reinterpret_cast<uint32_t*>(&h0);
            hsc1 = *reinterpret_cast<uint32_t*>(&h1);
        }
        int pb[16];
        #pragma unroll
        for (int j = 0; j < 16; j++) pb[j] = pcol[(size_t)j * NPACK];
        stage_A(0, 0);
        __syncthreads();   // tab ready before LUT use
        dequant_sts(pb, tabc, hsc0, hsc1, smem + SM_B, n0, kg);
        asm volatile("cp.async.wait_group 0;" ::: "memory");
        __syncthreads();
    }

    for (int i = 0; i < NK; i++) {
        const int p = i & 1;
        const int q = p ^ 1;
        const uint32_t abase = sbase + SM_A + p * 32768;
        const uint32_t bbase = sbase + SM_B + p * 16384;

        // ---- prefetch iter i+1 (LDG + cp.async issue before MMA) ----
        int pb[16];
        uint32_t hsc0 = 0, hsc1 = 0;
        const bool more = (i + 1 < NK);
        if (more) {
            const int k1 = (i + 1) * BK;
            const int g = k1 >> 7;
            __half2 h0 = __float2half2_rn(scp0[(size_t)g * N_FIXED]     * sv0);
            __half2 h1 = __float2half2_rn(scp0[(size_t)g * N_FIXED + 1] * sv1);
            hsc0 = *reinterpret_cast<uint32_t*>(&h0);
            hsc1 = *reinterpret_cast<uint32_t*>(&h1);
            const int* prow = pcol + (size_t)k1 * NPACK;
            #pragma unroll
            for (int j = 0; j < 16; j++) pb[j] = prow[(size_t)j * NPACK];
            stage_A(k1, q);
        }

        // ---- MMA for iter i: 4 k16 steps, warp tile 64x64 ----
        #pragma unroll
        for (int kk = 0; kk < 4; kk++) {
            const uint32_t kb = (uint32_t)(kk * 32 + khalf);
            uint32_t bf[8][2];
            #pragma unroll
            for (int nj = 0; nj < 4; nj++) {
                uint32_t ro = (uint32_t)((nw * 64 + nj * 16 + arow) * 128);
                uint32_t r0, r1, r2, r3;
                ldsm4(r0, r1, r2, r3, bbase + SW128(ro + kb));
                bf[2 * nj][0] = r0; bf[2 * nj][1] = r2;
                bf[2 * nj + 1][0] = r1; bf[2 * nj + 1][1] = r3;
            }
            #pragma unroll
            for (int mi = 0; mi < 4; mi++) {
                uint32_t ah[4];
                uint32_t ro = (uint32_t)((mw * 64 + mi * 16 + arow) * 128);
                ldsm4(ah[0], ah[1], ah[2], ah[3], abase + SW128(ro + kb));
                #pragma unroll
                for (int ni = 0; ni < 8; ni++)
                    mma16816(acc[mi][ni], ah, bf[ni]);
            }
        }

        // ---- dequant iter i+1 into stage q ----
        if (more) {
            dequant_sts(pb, tabc, hsc0, hsc1, smem + SM_B + q * 16384, n0, kg);
            asm volatile("cp.async.wait_group 0;" ::: "memory");
        }
        __syncthreads();
    }

    // ---- epilogue ----
    const int er = lid >> 2;
    const int ec = (lid & 3) * 2;
    #pragma unroll
    for (int mi = 0; mi < 4; mi++) {
        #pragma unroll
        for (int ni = 0; ni < 8; ni++) {
            int row = mbase + mw * 64 + mi * 16 + er;
            int col = nbase + nw * 64 + ni * 8 + ec;
            *reinterpret_cast<float2*>(out + (size_t)row * N_FIXED + col) =
                make_float2(acc[mi][ni][0], acc[mi][ni][1]);
            *reinterpret_cast<float2*>(out + (size_t)(row + 8) * N_FIXED + col) =
                make_float2(acc[mi][ni][2], acc[mi][ni][3]);
        }
    }
}

// ============ host launcher ============
extern "C" void kernel_launch(void* const* d_in, const int* in_sizes, int n_in,
                              void* d_out, int out_size)
{
    const float* x      = (const float*)d_in[0];
    const int*   packed = (const int*)  d_in[1];
    const float* grid   = (const float*)d_in[2];
    const float* scales = (const float*)d_in[3];
    const float* su     = (const float*)d_in[4];
    const float* sv     = (const float*)d_in[5];
    float* out = (float*)d_out;

    cudaFuncSetAttribute(trellis_mma_kernel,
                         cudaFuncAttributeMaxDynamicSharedMemorySize, SMEM_TOTAL);

    precompute_a<<<(M_FIXED * K_FIXED) / 1024, 256>>>(x, su);

    dim3 grd(M_FIXED / BM, N_FIXED / BN);
    trellis_mma_kernel<<<grd, NTHREADS, SMEM_TOTAL>>>(packed, grid, scales, sv, out);
}